// round 2
// baseline (speedup 1.0000x reference)
#include <cuda_runtime.h>
#include <cstdint>

// Problem constants
#define T_STEPS 512
#define B_TOT   256
#define H_TOT   512
#define N_POS   128
#define N_ACT   64
#define K_IN    192            // N_POS + N_ACT
#define K_TOT   704            // H_TOT + K_IN

// Tiling
#define H_PER_BLK 16           // h columns per block
#define N_HC      32           // H_TOT / H_PER_BLK
#define B_PER_BLK 64
#define N_BC      4            // B_TOT / B_PER_BLK
#define W_JSTRIDE (K_TOT * 4 + 8)   // 2824 words per j-row (4 gates interleaved, padded)
#define P_STRIDE  72                // panel smem row stride (32 k x 64 b, padded)
#define N_PANELS  22                // 704 / 32
#define SMEM_WORDS (H_PER_BLK * W_JSTRIDE + 32 * P_STRIDE + 64)
#define SMEM_BYTES (SMEM_WORDS * 4)

// Persistent device scratch (static allocation only — no cudaMalloc allowed)
__device__ float    g_hT[2][H_TOT * B_TOT];                     // transposed h ping-pong [j][b]
__device__ float    g_pout[T_STEPS * N_BC * N_HC * B_PER_BLK];  // partial output dot-products
__device__ unsigned g_count[N_BC];                              // barrier arrival counters
__device__ unsigned g_gen[N_BC];                                // barrier generations (monotonic)

typedef unsigned long long ull;

__device__ __forceinline__ ull pack2(float a, float b) {
    ull r; asm("mov.b64 %0, {%1, %2};" : "=l"(r) : "f"(a), "f"(b)); return r;
}
__device__ __forceinline__ void fma2(ull& d, ull a, ull b) {
    asm("fma.rn.f32x2 %0, %1, %2, %0;" : "+l"(d) : "l"(a), "l"(b));
}
__device__ __forceinline__ float2 unpack2(ull v) {
    float2 f; asm("mov.b64 {%0, %1}, %2;" : "=f"(f.x), "=f"(f.y) : "l"(v)); return f;
}
__device__ __forceinline__ float sigm(float x)  { return 1.f / (1.f + __expf(-x)); }
__device__ __forceinline__ float tanh_(float x) { return 2.f / (1.f + __expf(-2.f * x)) - 1.f; }

// ---------------------------------------------------------------------------
// Kernel 1: transpose h0 [B,H] -> g_hT[1] [H,B] (read buffer for t=0)
// ---------------------------------------------------------------------------
__global__ void init_h_kernel(const float* __restrict__ h0) {
    int g = blockIdx.x * blockDim.x + threadIdx.x;   // 131072 threads
    int j = g >> 8;
    int b = g & 255;
    g_hT[1][j * B_TOT + b] = h0[b * H_TOT + j];
}

// ---------------------------------------------------------------------------
// Kernel 2: persistent fused LSTM. grid = (N_HC, N_BC), 256 threads.
// Each block owns h-cols [j0, j0+16) x batch [b0, b0+64), holds its W slice
// (fp32, gate-interleaved) in SMEM for all 512 steps, c-state in registers.
// Per-batch-group (32 block) barrier per timestep.
// ---------------------------------------------------------------------------
__global__ void __launch_bounds__(256, 1)
lstm_kernel(const float* __restrict__ obs, const float* __restrict__ act,
            const float* __restrict__ c0,
            const float* __restrict__ W_ih, const float* __restrict__ W_hh,
            const float* __restrict__ b_ih, const float* __restrict__ b_hh,
            const float* __restrict__ W_out)
{
    extern __shared__ float smem[];
    float* W_sm    = smem;                              // [16][704][4] (+pad)
    float* p_sm    = smem + H_PER_BLK * W_JSTRIDE;      // [32][72] staging panel
    float* bias_sm = p_sm + 32 * P_STRIDE;              // [64]

    const int tid = threadIdx.x;
    const int tx  = tid & 15;     // j_local
    const int ty  = tid >> 4;     // batch group of 4
    const int hc  = blockIdx.x;
    const int bc  = blockIdx.y;
    const int j0  = hc * H_PER_BLK;
    const int b0  = bc * B_PER_BLK;

    // ---- one-time loads: W slice (gate-interleaved rows), combined bias ----
    for (int idx = tid; idx < H_PER_BLK * K_TOT * 4; idx += 256) {
        int j = idx / (K_TOT * 4);
        int r = idx - j * (K_TOT * 4);
        int k = r >> 2;
        int g = r & 3;
        int row = g * H_TOT + j0 + j;
        float v = (k < H_TOT) ? W_hh[row * H_TOT + k]
                              : W_ih[row * K_IN + (k - H_TOT)];
        W_sm[j * W_JSTRIDE + k * 4 + g] = v;
    }
    if (tid < 64) {
        int j = tid >> 2, g = tid & 3;
        int row = g * H_TOT + j0 + j;
        bias_sm[tid] = b_ih[row] + b_hh[row];
    }

    // ---- persistent per-thread state: c for 4 batch rows at column j0+tx ----
    float creg[4];
#pragma unroll
    for (int b4 = 0; b4 < 4; b4++)
        creg[b4] = c0[(b0 + ty * 4 + b4) * H_TOT + (j0 + tx)];
    const float wout = W_out[j0 + tx];

    unsigned base_gen = 0;
    if (tid == 0) base_gen = *((volatile unsigned*)&g_gen[bc]);
    __syncthreads();

    const float* Wp = W_sm + tx * W_JSTRIDE;
    const float* hp = p_sm + (ty << 2);

    for (int t = 0; t < T_STEPS; t++) {
        const float* hrd = g_hT[(t & 1) ^ 1];
        float*       hwr = g_hT[t & 1];

        // gate accumulators: f32x2 pairs, [batch-pair][gate], init with bias
        ull accA[4], accB[4];
#pragma unroll
        for (int g = 0; g < 4; g++) {
            float bi = bias_sm[tx * 4 + g];
            accA[g] = pack2(bi, bi);
            accB[g] = accA[g];
        }

#pragma unroll 1
        for (int p = 0; p < N_PANELS; p++) {
            // ---- stage K-panel of 32 into p_sm[k][b] ----
            if (p < 16) {
                // h panel from transposed global buffer (bypass L1: buffer reused)
                int k0 = p * 32;
                int kl = tid >> 3;
                int bq = tid & 7;
                const float* src = hrd + (k0 + kl) * B_TOT + b0 + bq * 8;
                float4 v0 = __ldcv((const float4*)src);
                float4 v1 = __ldcv((const float4*)(src + 4));
                float* dst = p_sm + kl * P_STRIDE + bq * 8;
                *(float4*)dst       = v0;
                *(float4*)(dst + 4) = v1;
            } else {
                // x panel from obs/act (transpose on the fly)
                int f0 = (p - 16) * 32;
                int bl = tid >> 2;
                int fq = tid & 3;
                int f  = f0 + fq * 8;
                float4 v0, v1;
                if (f0 < N_POS) {
                    const float* s = obs + ((size_t)(b0 + bl) * T_STEPS + t) * N_POS + f;
                    v0 = *(const float4*)s;  v1 = *(const float4*)(s + 4);
                } else {
                    const float* s = act + ((size_t)(b0 + bl) * T_STEPS + t) * N_ACT + (f - N_POS);
                    v0 = *(const float4*)s;  v1 = *(const float4*)(s + 4);
                }
                float tmp[8] = {v0.x, v0.y, v0.z, v0.w, v1.x, v1.y, v1.z, v1.w};
#pragma unroll
                for (int i = 0; i < 8; i++)
                    p_sm[(fq * 8 + i) * P_STRIDE + bl] = tmp[i];
            }
            __syncthreads();

            // ---- compute: 32 k-steps, 4 batch x 4 gates per thread, f32x2 ----
            const float* Wpp = Wp + p * 128;
#pragma unroll
            for (int k = 0; k < 32; k++) {
                float4 w = *(const float4*)(Wpp + k * 4);
                const float* hk = hp + k * P_STRIDE;
                ull a0 = *(const ull*)(hk);       // batch b0,b1
                ull a1 = *(const ull*)(hk + 2);   // batch b2,b3
                ull w0 = pack2(w.x, w.x); fma2(accA[0], a0, w0); fma2(accB[0], a1, w0);
                ull w1 = pack2(w.y, w.y); fma2(accA[1], a0, w1); fma2(accB[1], a1, w1);
                ull w2 = pack2(w.z, w.z); fma2(accA[2], a0, w2); fma2(accB[2], a1, w2);
                ull w3 = pack2(w.w, w.w); fma2(accA[3], a0, w3); fma2(accB[3], a1, w3);
            }
            __syncthreads();
        }

        // ---- activations + state update + h/partial-out writes ----
        float G[4][4];   // [b4][gate i,f,g,o]
#pragma unroll
        for (int g = 0; g < 4; g++) {
            float2 a = unpack2(accA[g]);
            float2 b = unpack2(accB[g]);
            G[0][g] = a.x; G[1][g] = a.y; G[2][g] = b.x; G[3][g] = b.y;
        }
        float po[4];
        float hv[4];
#pragma unroll
        for (int b4 = 0; b4 < 4; b4++) {
            float ii = sigm(G[b4][0]);
            float ff = sigm(G[b4][1]);
            float gg = tanh_(G[b4][2]);
            float oo = sigm(G[b4][3]);
            float cn = ff * creg[b4] + ii * gg;
            creg[b4] = cn;
            float hn = oo * tanh_(cn);
            hv[b4] = hn;
            po[b4] = hn * wout;
        }
        // h write: transposed layout, one STG.128 per thread, bypass L1
        __stcg((float4*)(hwr + (j0 + tx) * B_TOT + b0 + ty * 4),
               make_float4(hv[0], hv[1], hv[2], hv[3]));

        // partial output: reduce over the 16 j-columns of this block (tx lanes)
#pragma unroll
        for (int b4 = 0; b4 < 4; b4++) {
#pragma unroll
            for (int off = 1; off < 16; off <<= 1)
                po[b4] += __shfl_xor_sync(0xffffffffu, po[b4], off);
        }
        if (tx == 0) {
            float* pp = g_pout + (((size_t)t * N_BC + bc) * N_HC + hc) * B_PER_BLK + ty * 4;
            *(float4*)pp = make_float4(po[0], po[1], po[2], po[3]);
        }

        // ---- per-batch-group barrier (32 blocks) ----
        __syncthreads();
        if (tid == 0) {
            __threadfence();
            unsigned arr = atomicAdd(&g_count[bc], 1u);
            if (((arr + 1u) & 31u) == 0u) {
                atomicAdd(&g_gen[bc], 1u);
            } else {
                unsigned target = (unsigned)(t + 1);
                while ((*(volatile unsigned*)&g_gen[bc]) - base_gen < target)
                    __nanosleep(100);
            }
            __threadfence();
        }
        __syncthreads();
    }
}

// ---------------------------------------------------------------------------
// Kernel 3: reduce partial outputs -> out[b][t][0]
// ---------------------------------------------------------------------------
__global__ void out_kernel(const float* __restrict__ b_out, float* __restrict__ out) {
    int g = blockIdx.x * blockDim.x + threadIdx.x;   // 131072
    int bl   = g & 63;
    int rest = g >> 6;                 // t*4 + bc
    int bc = rest & 3;
    int t  = rest >> 2;
    const float* pp = g_pout + (size_t)rest * (N_HC * B_PER_BLK) + bl;
    float s = b_out[0];
#pragma unroll
    for (int h = 0; h < N_HC; h++) s += pp[h * B_PER_BLK];
    int b = bc * B_PER_BLK + bl;
    out[b * T_STEPS + t] = s;
}

// ---------------------------------------------------------------------------
extern "C" void kernel_launch(void* const* d_in, const int* in_sizes, int n_in,
                              void* d_out, int out_size) {
    const float* obs   = (const float*)d_in[0];
    const float* act   = (const float*)d_in[1];
    const float* h0    = (const float*)d_in[2];
    const float* c0    = (const float*)d_in[3];
    const float* W_ih  = (const float*)d_in[4];
    const float* W_hh  = (const float*)d_in[5];
    const float* b_ih  = (const float*)d_in[6];
    const float* b_hh  = (const float*)d_in[7];
    const float* W_out = (const float*)d_in[8];
    const float* b_out = (const float*)d_in[9];
    float* out = (float*)d_out;

    cudaFuncSetAttribute(lstm_kernel,
                         cudaFuncAttributeMaxDynamicSharedMemorySize, SMEM_BYTES);

    init_h_kernel<<<(H_TOT * B_TOT) / 256, 256>>>(h0);
    lstm_kernel<<<dim3(N_HC, N_BC), 256, SMEM_BYTES>>>(obs, act, c0, W_ih, W_hh,
                                                       b_ih, b_hh, W_out);
    out_kernel<<<(B_TOT * T_STEPS) / 256, 256>>>(b_out, out);
}

// round 4
// speedup vs baseline: 1.4858x; 1.4858x over previous
#include <cuda_runtime.h>
#include <cstdint>

// Problem constants
#define T_STEPS 512
#define B_TOT   256
#define H_TOT   512
#define N_POS   128
#define N_ACT   64
#define K_IN    192
#define K_TOT   704

// Tiling
#define H_PER_BLK 16
#define N_HC      32
#define B_PER_BLK 64
#define N_BC      4
#define N_PANELS  22              // q 0..3 obs, 4..5 act, 6..21 h
#define N_KP      352             // 704 / 2 k-pairs
#define W2_WORDS  45056           // 8 warps * 352 kp * 16 floats
#define W_SLAB    5632            // per-warp W2 slab (352*16)
#define PROW      34              // panel row stride (words): 32 data + 2 pad, 8B-aligned
#define PANEL_W   (64 * PROW)     // 2176 words
#define PANEL_B   (PANEL_W * 4)   // 8704 bytes
#define SMEM_WORDS (W2_WORDS + 2 * PANEL_W + 64 + 8 * 68 + 16)
#define SMEM_BYTES (SMEM_WORDS * 4)

// Static device scratch
__device__ float    g_hB[2][B_TOT * H_TOT];                     // h ping-pong, [b][j]
__device__ float    g_pout[T_STEPS * N_BC * N_HC * B_PER_BLK];
__device__ unsigned g_count[N_BC];
__device__ unsigned g_gen[N_BC];

typedef unsigned long long ull;

__device__ __forceinline__ ull pack2(float a, float b) {
    ull r; asm("mov.b64 %0, {%1, %2};" : "=l"(r) : "f"(a), "f"(b)); return r;
}
__device__ __forceinline__ void fma2(ull& d, ull a, ull b) {
    asm("fma.rn.f32x2 %0, %1, %2, %0;" : "+l"(d) : "l"(a), "l"(b));
}
__device__ __forceinline__ float2 unpack2(ull v) {
    float2 f; asm("mov.b64 {%0, %1}, %2;" : "=f"(f.x), "=f"(f.y) : "l"(v)); return f;
}
__device__ __forceinline__ float sigm(float x)  { return 1.f / (1.f + __expf(-x)); }
__device__ __forceinline__ float tanh_(float x) { return 2.f / (1.f + __expf(-2.f * x)) - 1.f; }

__device__ __forceinline__ void cp8(uint32_t dst, const float* src) {
    asm volatile("cp.async.ca.shared.global [%0], [%1], 8;" :: "r"(dst), "l"(src));
}
__device__ __forceinline__ void cp_commit() { asm volatile("cp.async.commit_group;"); }
__device__ __forceinline__ void cp_wait1()  { asm volatile("cp.async.wait_group 1;"); }
__device__ __forceinline__ void cp_wait0()  { asm volatile("cp.async.wait_group 0;"); }

// ---------------------------------------------------------------------------
// Copy h0 [B,H] -> g_hB[1] (same layout)
// ---------------------------------------------------------------------------
__global__ void init_h_kernel(const float* __restrict__ h0) {
    int g = blockIdx.x * blockDim.x + threadIdx.x;   // 131072
    g_hB[1][g] = h0[g];
}

// ---------------------------------------------------------------------------
// Persistent LSTM. grid (32 hc, 4 bc), 256 threads, 1 block/SM (smem-forced).
// Warp w owns gate-rows [8w, 8w+8) = j_locals {2w,2w+1} x 4 gates, all 64 b.
// Lane covers batches {lane, lane+32}. f32x2 accs pair adjacent k's.
// ---------------------------------------------------------------------------
__global__ void __launch_bounds__(256, 1)
lstm_kernel(const float* __restrict__ obs, const float* __restrict__ act,
            const float* __restrict__ c0,
            const float* __restrict__ W_ih, const float* __restrict__ W_hh,
            const float* __restrict__ b_ih, const float* __restrict__ b_hh,
            const float* __restrict__ W_out)
{
    extern __shared__ float smem[];
    float* W2      = smem;                       // [8][352][16]
    float* P0      = smem + W2_WORDS;            // 2 panels [64][34]
    float* bias_sm = P0 + 2 * PANEL_W;           // [64]
    float* posum   = bias_sm + 64;               // [8][68]

    const int tid  = threadIdx.x;
    const int lane = tid & 31;
    const int wid  = tid >> 5;
    const int hc   = blockIdx.x;
    const int bc   = blockIdx.y;
    const int j0   = hc * H_PER_BLK;
    const int b0   = bc * B_PER_BLK;

    const uint32_t p_u32 = (uint32_t)__cvta_generic_to_shared(P0);

    // ---- one-time: W2 fill. layout [w][q*16+kpl][r*2+par] ----
    for (int idx = tid; idx < W2_WORDS; idx += 256) {
        int w   = idx / W_SLAB;
        int rem = idx - w * W_SLAB;
        int kk  = rem >> 4;          // 0..351
        int e   = rem & 15;
        int q   = kk >> 4;
        int kpl = kk & 15;
        int r   = e >> 1;
        int par = e & 1;
        int r_blk = w * 8 + r;
        int jl   = r_blk >> 2;
        int gate = r_blk & 3;
        int row  = gate * H_TOT + j0 + jl;
        int base_k = (q < 6) ? (H_TOT + q * 32) : ((q - 6) * 32);
        int k = base_k + 2 * kpl + par;
        W2[idx] = (k < H_TOT) ? W_hh[row * H_TOT + k]
                              : W_ih[row * K_IN + (k - H_TOT)];
    }
    if (tid < 64) {
        int jl = tid >> 2, gate = tid & 3;
        int row = gate * H_TOT + j0 + jl;
        bias_sm[tid] = b_ih[row] + b_hh[row];
    }

    // ---- per-thread persistent state ----
    const int jg0 = j0 + 2 * wid;
    float2 clo = *(const float2*)(c0 + (size_t)(b0 + lane) * H_TOT + jg0);
    float2 chi = *(const float2*)(c0 + (size_t)(b0 + lane + 32) * H_TOT + jg0);
    const float2 wo = *(const float2*)(W_out + jg0);

    unsigned base_gen = 0;
    if (tid == 0) base_gen = *((volatile unsigned*)&g_gen[bc]);
    __syncthreads();

    const float* Wq_base = W2 + wid * W_SLAB;

    for (int t = 0; t < T_STEPS; t++) {
        const float* hrd = g_hB[(t & 1) ^ 1];
        float*       hwr = g_hB[t & 1];

        // stage panel q into buffer buf: 1024 cp8 chunks, warp-contiguous src
        auto issue = [&](int q, int buf) {
            uint32_t du = p_u32 + (buf ? PANEL_B : 0);
#pragma unroll
            for (int i = 0; i < 4; i++) {
                int c   = tid + 256 * i;
                int row = c >> 4;        // batch-local 0..63
                int col = c & 15;        // 8B chunk 0..15
                const float* src;
                if (q >= 6)
                    src = hrd + (size_t)(b0 + row) * H_TOT + (q - 6) * 32 + col * 2;
                else if (q < 4)
                    src = obs + ((size_t)(b0 + row) * T_STEPS + t) * N_POS + q * 32 + col * 2;
                else
                    src = act + ((size_t)(b0 + row) * T_STEPS + t) * N_ACT + (q - 4) * 32 + col * 2;
                cp8(du + (uint32_t)(row * PROW + col * 2) * 4, src);
            }
            cp_commit();
        };

        ull acc[16];
#pragma unroll
        for (int r = 0; r < 16; r++) acc[r] = 0ull;

        issue(0, 0);
        issue(1, 1);

#pragma unroll 1
        for (int q = 0; q < N_PANELS; q++) {
            if (q == N_PANELS - 1) cp_wait0(); else cp_wait1();
            __syncthreads();

            const float* P  = P0 + (q & 1) * PANEL_W;
            const float* Wq = Wq_base + q * 256;
            const float* h0p = P + lane * PROW;
            const float* h1p = P + (lane + 32) * PROW;
#pragma unroll
            for (int kpl = 0; kpl < 16; kpl++) {
                ull hA = *(const ull*)(h0p + 2 * kpl);
                ull hB = *(const ull*)(h1p + 2 * kpl);
                longlong2 w01 = *(const longlong2*)(Wq + kpl * 16);
                longlong2 w23 = *(const longlong2*)(Wq + kpl * 16 + 4);
                longlong2 w45 = *(const longlong2*)(Wq + kpl * 16 + 8);
                longlong2 w67 = *(const longlong2*)(Wq + kpl * 16 + 12);
                fma2(acc[0], hA, (ull)w01.x); fma2(acc[8],  hB, (ull)w01.x);
                fma2(acc[1], hA, (ull)w01.y); fma2(acc[9],  hB, (ull)w01.y);
                fma2(acc[2], hA, (ull)w23.x); fma2(acc[10], hB, (ull)w23.x);
                fma2(acc[3], hA, (ull)w23.y); fma2(acc[11], hB, (ull)w23.y);
                fma2(acc[4], hA, (ull)w45.x); fma2(acc[12], hB, (ull)w45.x);
                fma2(acc[5], hA, (ull)w45.y); fma2(acc[13], hB, (ull)w45.y);
                fma2(acc[6], hA, (ull)w67.x); fma2(acc[14], hB, (ull)w67.x);
                fma2(acc[7], hA, (ull)w67.y); fma2(acc[15], hB, (ull)w67.y);
            }
            __syncthreads();

            int qn = q + 2;
            if (qn < N_PANELS) {
                if (qn == 6 && t > 0) {
                    // all 32 blocks of this batch group must have written h_t;
                    // the gpu-scope fence also flushes L1D (CCTL.IVALL) so the
                    // .ca h-panel loads below cannot hit stale lines.
                    if (tid == 0) {
                        while ((*(volatile unsigned*)&g_gen[bc]) - base_gen < (unsigned)t)
                            __nanosleep(32);
                        __threadfence();
                    }
                    __syncthreads();
                }
                issue(qn, q & 1);
            }
        }

        // ---- merge k-parity halves + bias ----
        float s[16];
#pragma unroll
        for (int r = 0; r < 16; r++) {
            float2 v = unpack2(acc[r]);
            s[r] = v.x + v.y + bias_sm[wid * 8 + (r & 7)];
        }

        // ---- activations: 4 cells = {b_lo,b_hi} x {j0,j1} ----
        float h_lo0, h_lo1, h_hi0, h_hi1;
        {
            float ii, ff, gg, oo, cn;
            ii = sigm(s[0]);  ff = sigm(s[1]);  gg = tanh_(s[2]);  oo = sigm(s[3]);
            cn = ff * clo.x + ii * gg;  clo.x = cn;  h_lo0 = oo * tanh_(cn);
            ii = sigm(s[4]);  ff = sigm(s[5]);  gg = tanh_(s[6]);  oo = sigm(s[7]);
            cn = ff * clo.y + ii * gg;  clo.y = cn;  h_lo1 = oo * tanh_(cn);
            ii = sigm(s[8]);  ff = sigm(s[9]);  gg = tanh_(s[10]); oo = sigm(s[11]);
            cn = ff * chi.x + ii * gg;  chi.x = cn;  h_hi0 = oo * tanh_(cn);
            ii = sigm(s[12]); ff = sigm(s[13]); gg = tanh_(s[14]); oo = sigm(s[15]);
            cn = ff * chi.y + ii * gg;  chi.y = cn;  h_hi1 = oo * tanh_(cn);
        }

        // h writes (L2; readers are cp.async after L1 flush)
        __stcg((float2*)(hwr + (size_t)(b0 + lane) * H_TOT + jg0),
               make_float2(h_lo0, h_lo1));
        __stcg((float2*)(hwr + (size_t)(b0 + lane + 32) * H_TOT + jg0),
               make_float2(h_hi0, h_hi1));

        // output partials: per-warp j-pair contribution, reduce across warps
        posum[wid * 68 + lane]      = h_lo0 * wo.x + h_lo1 * wo.y;
        posum[wid * 68 + lane + 32] = h_hi0 * wo.x + h_hi1 * wo.y;
        __syncthreads();
        if (tid < 64) {
            float sum = 0.f;
#pragma unroll
            for (int w = 0; w < 8; w++) sum += posum[w * 68 + tid];
            g_pout[(((size_t)t * N_BC + bc) * N_HC + hc) * B_PER_BLK + tid] = sum;
        }

        // arrive (wait is overlapped with next step's x panels)
        if (tid == 0) {
            __threadfence();
            unsigned arr = atomicAdd(&g_count[bc], 1u);
            if (((arr + 1u) & 31u) == 0u)
                atomicAdd(&g_gen[bc], 1u);
        }
        __syncthreads();
    }
}

// ---------------------------------------------------------------------------
// Reduce partial outputs -> out[b][t]
// ---------------------------------------------------------------------------
__global__ void out_kernel(const float* __restrict__ b_out, float* __restrict__ out) {
    int g = blockIdx.x * blockDim.x + threadIdx.x;   // 131072
    int bl   = g & 63;
    int rest = g >> 6;
    int bc = rest & 3;
    int t  = rest >> 2;
    const float* pp = g_pout + (size_t)rest * (N_HC * B_PER_BLK) + bl;
    float s = b_out[0];
#pragma unroll
    for (int h = 0; h < N_HC; h++) s += pp[h * B_PER_BLK];
    int b = bc * B_PER_BLK + bl;
    out[b * T_STEPS + t] = s;
}

// ---------------------------------------------------------------------------
extern "C" void kernel_launch(void* const* d_in, const int* in_sizes, int n_in,
                              void* d_out, int out_size) {
    const float* obs   = (const float*)d_in[0];
    const float* act   = (const float*)d_in[1];
    const float* h0    = (const float*)d_in[2];
    const float* c0    = (const float*)d_in[3];
    const float* W_ih  = (const float*)d_in[4];
    const float* W_hh  = (const float*)d_in[5];
    const float* b_ih  = (const float*)d_in[6];
    const float* b_hh  = (const float*)d_in[7];
    const float* W_out = (const float*)d_in[8];
    const float* b_out = (const float*)d_in[9];
    float* out = (float*)d_out;

    cudaFuncSetAttribute(lstm_kernel,
                         cudaFuncAttributeMaxDynamicSharedMemorySize, SMEM_BYTES);

    init_h_kernel<<<(B_TOT * H_TOT) / 256, 256>>>(h0);
    lstm_kernel<<<dim3(N_HC, N_BC), 256, SMEM_BYTES>>>(obs, act, c0, W_ih, W_hh,
                                                       b_ih, b_hh, W_out);
    out_kernel<<<(B_TOT * T_STEPS) / 256, 256>>>(b_out, out);
}